// round 10
// baseline (speedup 1.0000x reference)
#include <cuda_runtime.h>

// VariantCoeLinear1d: 1D Rusanov FV solver, 128 rows x 2048 pts x 256 steps.
// One CTA per row (128 CTAs, single wave). 512 threads x 4 register points.
//
// R10 = R7 with the CTA-wide __syncthreads replaced by NEIGHBOR-ONLY
// producer/consumer sync: per-warp SMEM step counters, published with
// st.release.cta.shared after a __syncwarp, consumed with ld.acquire spin.
// Warps pipeline instead of marching in lockstep, absorbing arbiter skew /
// LDS latency / STG issue cost that caused R7's 29% issue idle.
// 2 parity halo buffers; acquire/release chain bounds neighbor lead to 1
// step -> no clobber, monotone counters -> no deadlock.

#define BATCH 128
#define NPTS  2048
#define STEPS 256
#define TPB   512
#define NW    (TPB / 32)
#define PPT   4   // TPB*PPT == NPTS

typedef unsigned long long u64;

static __device__ __forceinline__ u64 pk(float lo, float hi) {
    u64 r; asm("mov.b64 %0,{%1,%2};" : "=l"(r) : "f"(lo), "f"(hi)); return r;
}
static __device__ __forceinline__ void upk(float& lo, float& hi, u64 v) {
    asm("mov.b64 {%0,%1},%2;" : "=f"(lo), "=f"(hi) : "l"(v));
}
static __device__ __forceinline__ u64 f2fma(u64 a, u64 b, u64 c) {
    u64 d; asm("fma.rn.f32x2 %0,%1,%2,%3;" : "=l"(d) : "l"(a), "l"(b), "l"(c)); return d;
}
static __device__ __forceinline__ u64 f2mul(u64 a, u64 b) {
    u64 d; asm("mul.rn.f32x2 %0,%1,%2;" : "=l"(d) : "l"(a), "l"(b)); return d;
}

// fh = (f_l + f_r) - max(a_l,a_r) * (u_r - u_l)   (0.5 folded into HL)
static __device__ __forceinline__ float iface(float ul, float fl, float al,
                                              float ur, float fr, float ar) {
    float am = fmaxf(al, ar);
    return fmaf(-am, ur - ul, fl + fr);
}

// Horner pack: f and |f'| for two points, 10 f32x2 ops.
#define POLY_PACK(U, FLO, FHI, ALO, AHI)                                   \
    do {                                                                   \
        u64 _u2 = f2mul(U, U);                                             \
        u64 _t  = f2fma(CB6, _u2, CB4);                                    \
        _t      = f2fma(_t, U, CB3);                                       \
        _t      = f2fma(_t, U, CB2);                                       \
        _t      = f2fma(_t, U, CB1);                                       \
        u64 _F  = f2mul(_t, U);                                            \
        u64 _s  = f2fma(CA5, _u2, CA3);                                    \
        _s      = f2fma(_s, U, CA2);                                       \
        _s      = f2fma(_s, U, CA1);                                       \
        _s      = f2fma(_s, U, CA0);                                       \
        u64 _A  = _s & ABSM;                                               \
        upk(FLO, FHI, _F);                                                 \
        upk(ALO, AHI, _A);                                                 \
    } while (0)

__global__ void __launch_bounds__(TPB, 1)
vcl_kernel(const float* __restrict__ init, float* __restrict__ out)
{
    __shared__ float sL[2][TPB];   // thread t's FIRST point
    __shared__ float sR[2][TPB];   // thread t's LAST point
    __shared__ int   ctr[NW];      // per-warp published-step counter

    const int row  = blockIdx.x;
    const int tid  = threadIdx.x;
    const int lane = tid & 31;
    const int wid  = tid >> 5;
    const int base = tid * PPT;
    const int tl   = (tid > 0) ? tid - 1 : 0;              // edge dummies:
    const int tr   = (tid < TPB - 1) ? tid + 1 : TPB - 1;  // overwritten by BC
    const float HL = 0.5f * (float)(0.002 / (10.0 / 2048.0));  // 0.5*dt/dx

    // neighbor counters (edge warps point at self: always satisfied)
    const int wl = (wid > 0) ? wid - 1 : wid;
    const int wr = (wid < NW - 1) ? wid + 1 : wid;
    const unsigned aL  = (unsigned)__cvta_generic_to_shared(&ctr[wl]);
    const unsigned aR  = (unsigned)__cvta_generic_to_shared(&ctr[wr]);
    const unsigned aMe = (unsigned)__cvta_generic_to_shared(&ctr[wid]);

    const double c = 0.1 / 12.0;   // beta/12
    const u64 CB1 = pk(1.5f, 1.5f);
    const u64 CB2 = pk((float)(0.75 * c),        (float)(0.75 * c));
    const u64 CB3 = pk((float)(-0.5 - 2.0 * c),  (float)(-0.5 - 2.0 * c));
    const u64 CB4 = pk((float)(1.5 * c),         (float)(1.5 * c));
    const u64 CB6 = pk((float)(-0.25 * c),       (float)(-0.25 * c));
    const u64 CA0 = pk(1.5f, 1.5f);
    const u64 CA1 = pk((float)(1.5 * c),         (float)(1.5 * c));
    const u64 CA2 = pk((float)(-1.5 - 6.0 * c),  (float)(-1.5 - 6.0 * c));
    const u64 CA3 = pk((float)(6.0 * c),         (float)(6.0 * c));
    const u64 CA5 = pk((float)(-1.5 * c),        (float)(-1.5 * c));
    const u64 ABSM = 0x7fffffff7fffffffULL;

    float u0, u1, u2, u3;
    {
        const float4* ip = reinterpret_cast<const float4*>(init + (size_t)row * NPTS + base);
        float4 a0 = ip[0];
        u0 = a0.x; u1 = a0.y; u2 = a0.z; u3 = a0.w;
        float4* o0 = reinterpret_cast<float4*>(out + (size_t)row * NPTS + base);
        __stcs(o0, a0);
    }
    // initial publish (state 0 -> buffer 0) + counter init; one CTA barrier
    sL[0][tid] = u0;
    sR[0][tid] = u3;
    if (lane == 0) ctr[wid] = 0;
    __syncthreads();

    float4* op = reinterpret_cast<float4*>(out + ((size_t)BATCH + row) * NPTS + base);
    const size_t ostride = (size_t)BATCH * NPTS / 4;

    #pragma unroll 2
    for (int s = 1; s < STEPS; ++s) {
        const int b    = (s - 1) & 1;   // buffer holding state s-1
        const int need = s - 1;

        // ---- wait (neighbor-only) until warps w±1 published step s-1 ----
        int vL, vR;
        do {
            asm volatile(
                "ld.acquire.cta.shared.b32 %0,[%2];\n\t"
                "ld.acquire.cta.shared.b32 %1,[%3];"
                : "=r"(vL), "=r"(vR) : "r"(aL), "r"(aR) : "memory");
        } while (vL < need || vR < need);

        float um = sR[b][tl];
        float up = sL[b][tr];

        // ---- flux + |flux'|: 2 owned packs + 1 halo pack ----
        float f0, f1, a0, a1, f2, f3, a2, a3, fm, fp2, am, ap;
        { u64 U = pk(u0, u1); POLY_PACK(U, f0, f1, a0, a1); }
        { u64 U = pk(u2, u3); POLY_PACK(U, f2, f3, a2, a3); }
        { u64 U = pk(um, up); POLY_PACK(U, fm, fp2, am, ap); }

        // ---- interfaces + updates ----
        float h0 = iface(um, fm, am, u0, f0, a0);
        float h1 = iface(u0, f0, a0, u1, f1, a1);
        float h2 = iface(u1, f1, a1, u2, f2, a2);
        float h3 = iface(u2, f2, a2, u3, f3, a3);
        float h4 = iface(u3, f3, a3, up, fp2, ap);

        float un0 = fmaf(-HL, h1 - h0, u0);
        float un1 = fmaf(-HL, h2 - h1, u1);
        float un2 = fmaf(-HL, h3 - h2, u2);
        float un3 = fmaf(-HL, h4 - h3, u3);
        if (tid == 0)       un0 = un1;   // outflow BC
        if (tid == TPB - 1) un3 = un2;

        // ---- publish state s ASAP: STS -> syncwarp -> release counter ----
        const int nb = s & 1;
        sL[nb][tid] = un0;
        sR[nb][tid] = un3;
        __syncwarp();
        if (lane == 0)
            asm volatile("st.release.cta.shared.b32 [%0],%1;"
                         :: "r"(aMe), "r"(s) : "memory");

        // ---- stream frame (write-only; evict-first) ----
        __stcs(op, make_float4(un0, un1, un2, un3));
        op += ostride;

        u0 = un0; u1 = un1; u2 = un2; u3 = un3;
    }
}

extern "C" void kernel_launch(void* const* d_in, const int* in_sizes, int n_in,
                              void* d_out, int out_size) {
    const float* init = (const float*)d_in[0];   // [128, 2048] fp32
    // d_in[1] = stepnum (int32) — fixed at 256 by the problem spec
    float* out = (float*)d_out;                  // [256, 128, 2048] fp32
    vcl_kernel<<<BATCH, TPB>>>(init, out);
}

// round 11
// speedup vs baseline: 1.0838x; 1.0838x over previous
#include <cuda_runtime.h>

// VariantCoeLinear1d: 1D Rusanov FV solver, 128 rows x 2048 pts x 256 steps.
// One CTA per row (128 CTAs, single wave). 512 threads x 4 register points.
//
// R11 = R7 (best: 63.8us) with the per-step STG.128 output (12-cyc issue
// cost, ~10% of the step budget) replaced by STS.128 into a 4-deep ring of
// 8KB SMEM frame buffers + a single-thread cp.async.bulk (shared->global,
// bulk_group) issued for the PREVIOUS frame right after the existing
// top-of-step barrier (which fences those STS). wait_group<=2 placed BEFORE
// the barrier publishes copy completion to all threads before buffer reuse
// (ring 4 => ~3 steps of copy-latency budget). Output moves to the TMA/LSU
// bulk path, freeing SM issue slots.

#define BATCH 128
#define NPTS  2048
#define STEPS 256
#define TPB   512
#define PPT   4   // TPB*PPT == NPTS

typedef unsigned long long u64;

static __device__ __forceinline__ u64 pk(float lo, float hi) {
    u64 r; asm("mov.b64 %0,{%1,%2};" : "=l"(r) : "f"(lo), "f"(hi)); return r;
}
static __device__ __forceinline__ void upk(float& lo, float& hi, u64 v) {
    asm("mov.b64 {%0,%1},%2;" : "=f"(lo), "=f"(hi) : "l"(v));
}
static __device__ __forceinline__ u64 f2fma(u64 a, u64 b, u64 c) {
    u64 d; asm("fma.rn.f32x2 %0,%1,%2,%3;" : "=l"(d) : "l"(a), "l"(b), "l"(c)); return d;
}
static __device__ __forceinline__ u64 f2mul(u64 a, u64 b) {
    u64 d; asm("mul.rn.f32x2 %0,%1,%2;" : "=l"(d) : "l"(a), "l"(b)); return d;
}

// fh = (f_l + f_r) - max(a_l,a_r) * (u_r - u_l)   (0.5 folded into HL)
static __device__ __forceinline__ float iface(float ul, float fl, float al,
                                              float ur, float fr, float ar) {
    float am = fmaxf(al, ar);
    return fmaf(-am, ur - ul, fl + fr);
}

// Horner pack: f and |f'| for two points, 10 f32x2 ops.
#define POLY_PACK(U, FLO, FHI, ALO, AHI)                                   \
    do {                                                                   \
        u64 _u2 = f2mul(U, U);                                             \
        u64 _t  = f2fma(CB6, _u2, CB4);                                    \
        _t      = f2fma(_t, U, CB3);                                       \
        _t      = f2fma(_t, U, CB2);                                       \
        _t      = f2fma(_t, U, CB1);                                       \
        u64 _F  = f2mul(_t, U);                                            \
        u64 _s  = f2fma(CA5, _u2, CA3);                                    \
        _s      = f2fma(_s, U, CA2);                                       \
        _s      = f2fma(_s, U, CA1);                                       \
        _s      = f2fma(_s, U, CA0);                                       \
        u64 _A  = _s & ABSM;                                               \
        upk(FLO, FHI, _F);                                                 \
        upk(ALO, AHI, _A);                                                 \
    } while (0)

__global__ void __launch_bounds__(TPB, 1)
vcl_kernel(const float* __restrict__ init, float* __restrict__ out)
{
    __shared__ float sL[2][TPB];   // thread t's FIRST point (double-buffered)
    __shared__ float sR[2][TPB];   // thread t's LAST point
    __shared__ __align__(16) float4 frame[4][TPB];   // output staging ring

    const int row  = blockIdx.x;
    const int tid  = threadIdx.x;
    const int base = tid * PPT;
    const int tl   = (tid > 0) ? tid - 1 : 0;              // edge dummies:
    const int tr   = (tid < TPB - 1) ? tid + 1 : TPB - 1;  // overwritten by BC
    const float HL = 0.5f * (float)(0.002 / (10.0 / 2048.0));  // 0.5*dt/dx

    const double c = 0.1 / 12.0;   // beta/12
    const u64 CB1 = pk(1.5f, 1.5f);
    const u64 CB2 = pk((float)(0.75 * c),        (float)(0.75 * c));
    const u64 CB3 = pk((float)(-0.5 - 2.0 * c),  (float)(-0.5 - 2.0 * c));
    const u64 CB4 = pk((float)(1.5 * c),         (float)(1.5 * c));
    const u64 CB6 = pk((float)(-0.25 * c),       (float)(-0.25 * c));
    const u64 CA0 = pk(1.5f, 1.5f);
    const u64 CA1 = pk((float)(1.5 * c),         (float)(1.5 * c));
    const u64 CA2 = pk((float)(-1.5 - 6.0 * c),  (float)(-1.5 - 6.0 * c));
    const u64 CA3 = pk((float)(6.0 * c),         (float)(6.0 * c));
    const u64 CA5 = pk((float)(-1.5 * c),        (float)(-1.5 * c));
    const u64 ABSM = 0x7fffffff7fffffffULL;

    // smem addresses of the 4 frame buffers (32-bit shared window)
    const unsigned fr0 = (unsigned)__cvta_generic_to_shared(&frame[0][0]);
    const unsigned FRB = (unsigned)(TPB * 16);   // 8192 bytes per frame

    float u0, u1, u2, u3;
    {
        const float4* ip = reinterpret_cast<const float4*>(init + (size_t)row * NPTS + base);
        float4 a0 = ip[0];
        u0 = a0.x; u1 = a0.y; u2 = a0.z; u3 = a0.w;
        // frame 0 = init: direct streaming store (one-time)
        float4* o0 = reinterpret_cast<float4*>(out + (size_t)row * NPTS + base);
        __stcs(o0, a0);
    }
    sL[0][tid] = u0;
    sR[0][tid] = u3;

    #pragma unroll 1
    for (int s = 1; s < STEPS; ++s) {
        // ---- bound outstanding bulk copies BEFORE the barrier so the
        //      barrier release publishes completion to all threads ----
        if (tid == 0)
            asm volatile("cp.async.bulk.wait_group 2;" ::: "memory");
        __syncthreads();   // fences prev step's STS (halo + frame) + the wait

        // ---- issue bulk copy of the PREVIOUS frame (state s-1) ----
        if (tid == 0 && s > 1) {
            float* gdst = out + ((size_t)(s - 1) * BATCH + row) * NPTS;
            unsigned src = fr0 + ((unsigned)(s - 1) & 3u) * FRB;
            asm volatile("fence.proxy.async.shared::cta;" ::: "memory");
            asm volatile(
                "cp.async.bulk.global.shared::cta.bulk_group [%0], [%1], %2;"
                :: "l"(gdst), "r"(src), "r"((unsigned)(TPB * 16)) : "memory");
            asm volatile("cp.async.bulk.commit_group;" ::: "memory");
        }

        // ---- halo u loads (state s-1) ----
        const int b = (s - 1) & 1;
        float um = sR[b][tl];
        float up = sL[b][tr];

        // ---- flux + |flux'|: 2 owned packs + 1 halo pack ----
        float f0, f1, a0, a1, f2, f3, a2, a3, fm, fp2, am, ap;
        { u64 U = pk(u0, u1); POLY_PACK(U, f0, f1, a0, a1); }
        { u64 U = pk(u2, u3); POLY_PACK(U, f2, f3, a2, a3); }
        { u64 U = pk(um, up); POLY_PACK(U, fm, fp2, am, ap); }

        // ---- interfaces + updates ----
        float h0 = iface(um, fm, am, u0, f0, a0);
        float h1 = iface(u0, f0, a0, u1, f1, a1);
        float h2 = iface(u1, f1, a1, u2, f2, a2);
        float h3 = iface(u2, f2, a2, u3, f3, a3);
        float h4 = iface(u3, f3, a3, up, fp2, ap);

        float un0 = fmaf(-HL, h1 - h0, u0);
        float un1 = fmaf(-HL, h2 - h1, u1);
        float un2 = fmaf(-HL, h3 - h2, u2);
        float un3 = fmaf(-HL, h4 - h3, u3);
        if (tid == 0)       un0 = un1;   // outflow BC
        if (tid == TPB - 1) un3 = un2;

        // ---- stage frame s in SMEM ring (copied at step s+1) ----
        frame[s & 3][tid] = make_float4(un0, un1, un2, un3);

        // ---- publish next-step boundaries ----
        sL[s & 1][tid] = un0;
        sR[s & 1][tid] = un3;

        u0 = un0; u1 = un1; u2 = un2; u3 = un3;
    }

    // ---- flush the last frame (state 255) ----
    __syncthreads();   // fence final STS
    if (tid == 0) {
        float* gdst = out + ((size_t)(STEPS - 1) * BATCH + row) * NPTS;
        unsigned src = fr0 + ((unsigned)(STEPS - 1) & 3u) * FRB;
        asm volatile("fence.proxy.async.shared::cta;" ::: "memory");
        asm volatile(
            "cp.async.bulk.global.shared::cta.bulk_group [%0], [%1], %2;"
            :: "l"(gdst), "r"(src), "r"((unsigned)(TPB * 16)) : "memory");
        asm volatile("cp.async.bulk.commit_group;" ::: "memory");
        asm volatile("cp.async.bulk.wait_group 0;" ::: "memory");
    }
}

extern "C" void kernel_launch(void* const* d_in, const int* in_sizes, int n_in,
                              void* d_out, int out_size) {
    const float* init = (const float*)d_in[0];   // [128, 2048] fp32
    // d_in[1] = stepnum (int32) — fixed at 256 by the problem spec
    float* out = (float*)d_out;                  // [256, 128, 2048] fp32
    vcl_kernel<<<BATCH, TPB>>>(init, out);
}

// round 12
// speedup vs baseline: 1.4152x; 1.3058x over previous
#include <cuda_runtime.h>

// VariantCoeLinear1d: 1D Rusanov FV solver, 128 rows x 2048 pts x 256 steps.
// One CTA per row (128 CTAs, single wave). 512 threads x 4 register points.
//
// R12 = R7 (best: 63.8us) with overhead isolated and removed, nothing else:
//  - step loop unrolled 2x: buffer index s&1 becomes compile-time per copy
//    (SMEM addresses fold to immediates, cutting ALU addressing ops) and the
//    u<-un register copies vanish via renaming.
//  - outflow-BC predicates hoisted out of the loop.
// Structure, arithmetic, and memory pattern are otherwise identical to R7.

#define BATCH 128
#define NPTS  2048
#define STEPS 256
#define TPB   512
#define PPT   4   // TPB*PPT == NPTS

typedef unsigned long long u64;

static __device__ __forceinline__ u64 pk(float lo, float hi) {
    u64 r; asm("mov.b64 %0,{%1,%2};" : "=l"(r) : "f"(lo), "f"(hi)); return r;
}
static __device__ __forceinline__ void upk(float& lo, float& hi, u64 v) {
    asm("mov.b64 {%0,%1},%2;" : "=f"(lo), "=f"(hi) : "l"(v));
}
static __device__ __forceinline__ u64 f2fma(u64 a, u64 b, u64 c) {
    u64 d; asm("fma.rn.f32x2 %0,%1,%2,%3;" : "=l"(d) : "l"(a), "l"(b), "l"(c)); return d;
}
static __device__ __forceinline__ u64 f2mul(u64 a, u64 b) {
    u64 d; asm("mul.rn.f32x2 %0,%1,%2;" : "=l"(d) : "l"(a), "l"(b)); return d;
}

// fh = (f_l + f_r) - max(a_l,a_r) * (u_r - u_l)   (0.5 folded into HL)
static __device__ __forceinline__ float iface(float ul, float fl, float al,
                                              float ur, float fr, float ar) {
    float am = fmaxf(al, ar);
    return fmaf(-am, ur - ul, fl + fr);
}

// Horner pack: f and |f'| for two points, 10 f32x2 ops.
#define POLY_PACK(U, FLO, FHI, ALO, AHI)                                   \
    do {                                                                   \
        u64 _u2 = f2mul(U, U);                                             \
        u64 _t  = f2fma(CB6, _u2, CB4);                                    \
        _t      = f2fma(_t, U, CB3);                                       \
        _t      = f2fma(_t, U, CB2);                                       \
        _t      = f2fma(_t, U, CB1);                                       \
        u64 _F  = f2mul(_t, U);                                            \
        u64 _s  = f2fma(CA5, _u2, CA3);                                    \
        _s      = f2fma(_s, U, CA2);                                       \
        _s      = f2fma(_s, U, CA1);                                       \
        _s      = f2fma(_s, U, CA0);                                       \
        u64 _A  = _s & ABSM;                                               \
        upk(FLO, FHI, _F);                                                 \
        upk(ALO, AHI, _A);                                                 \
    } while (0)

__global__ void __launch_bounds__(TPB, 1)
vcl_kernel(const float* __restrict__ init, float* __restrict__ out)
{
    __shared__ float sL[2][TPB];   // thread t's FIRST point
    __shared__ float sR[2][TPB];   // thread t's LAST point

    const int row  = blockIdx.x;
    const int tid  = threadIdx.x;
    const int base = tid * PPT;
    const int tl   = (tid > 0) ? tid - 1 : 0;              // edge dummies:
    const int tr   = (tid < TPB - 1) ? tid + 1 : TPB - 1;  // overwritten by BC
    const bool e0  = (tid == 0);                            // hoisted BC preds
    const bool e1  = (tid == TPB - 1);
    const float HL = 0.5f * (float)(0.002 / (10.0 / 2048.0));  // 0.5*dt/dx

    const double c = 0.1 / 12.0;   // beta/12
    const u64 CB1 = pk(1.5f, 1.5f);
    const u64 CB2 = pk((float)(0.75 * c),        (float)(0.75 * c));
    const u64 CB3 = pk((float)(-0.5 - 2.0 * c),  (float)(-0.5 - 2.0 * c));
    const u64 CB4 = pk((float)(1.5 * c),         (float)(1.5 * c));
    const u64 CB6 = pk((float)(-0.25 * c),       (float)(-0.25 * c));
    const u64 CA0 = pk(1.5f, 1.5f);
    const u64 CA1 = pk((float)(1.5 * c),         (float)(1.5 * c));
    const u64 CA2 = pk((float)(-1.5 - 6.0 * c),  (float)(-1.5 - 6.0 * c));
    const u64 CA3 = pk((float)(6.0 * c),         (float)(6.0 * c));
    const u64 CA5 = pk((float)(-1.5 * c),        (float)(-1.5 * c));
    const u64 ABSM = 0x7fffffff7fffffffULL;

    float u0, u1, u2, u3;
    {
        const float4* ip = reinterpret_cast<const float4*>(init + (size_t)row * NPTS + base);
        float4 a0 = ip[0];
        u0 = a0.x; u1 = a0.y; u2 = a0.z; u3 = a0.w;
        float4* o0 = reinterpret_cast<float4*>(out + (size_t)row * NPTS + base);
        __stcs(o0, a0);
    }
    sL[0][tid] = u0;
    sR[0][tid] = u3;

    float4* op = reinterpret_cast<float4*>(out + ((size_t)BATCH + row) * NPTS + base);
    const size_t ostride = (size_t)BATCH * NPTS / 4;

    #pragma unroll 2
    for (int s = 1; s < STEPS; ++s) {
        const int b = (s - 1) & 1;   // compile-time 0/1 per unrolled copy

        // ======== pre-barrier: owned polys + interior interfaces/updates ====
        float f0, f1, a0, a1, f2, f3, a2, a3;
        { u64 U = pk(u0, u1); POLY_PACK(U, f0, f1, a0, a1); }
        { u64 U = pk(u2, u3); POLY_PACK(U, f2, f3, a2, a3); }

        float h1 = iface(u0, f0, a0, u1, f1, a1);
        float h2 = iface(u1, f1, a1, u2, f2, a2);
        float h3 = iface(u2, f2, a2, u3, f3, a3);
        float un1 = fmaf(-HL, h2 - h1, u1);
        float un2 = fmaf(-HL, h3 - h2, u2);

        // ======== barrier separates prev-step publishes from halo reads ====
        __syncthreads();

        float um = sR[b][tl];
        float up = sL[b][tr];

        float fm, fp2, am, ap;
        { u64 U = pk(um, up); POLY_PACK(U, fm, fp2, am, ap); }

        float h0 = iface(um, fm, am, u0, f0, a0);
        float h4 = iface(u3, f3, a3, up, fp2, ap);
        float un0 = fmaf(-HL, h1 - h0, u0);
        float un3 = fmaf(-HL, h4 - h3, u3);

        if (e0) un0 = un1;   // outflow BC (hoisted predicates)
        if (e1) un3 = un2;

        // publish next-step boundaries (other buffer; next barrier fences)
        const int nb = s & 1;
        sL[nb][tid] = un0;
        sR[nb][tid] = un3;

        // stream frame (write-only; evict-first)
        __stcs(op, make_float4(un0, un1, un2, un3));
        op += ostride;

        u0 = un0; u1 = un1; u2 = un2; u3 = un3;
    }
}

extern "C" void kernel_launch(void* const* d_in, const int* in_sizes, int n_in,
                              void* d_out, int out_size) {
    const float* init = (const float*)d_in[0];   // [128, 2048] fp32
    // d_in[1] = stepnum (int32) — fixed at 256 by the problem spec
    float* out = (float*)d_out;                  // [256, 128, 2048] fp32
    vcl_kernel<<<BATCH, TPB>>>(init, out);
}